// round 7
// baseline (speedup 1.0000x reference)
#include <cuda_runtime.h>

#define GRID_C 8
#define VOX    128
#define NB     16
#define VOX3   (VOX * VOX * VOX)
#define TOTAL  (NB * VOX3)

// Coarse flow field after cumsum: [b][c][d][h][w], 16*3*512 floats = 96 KB
__device__ float g_flow[NB * 3 * GRID_C * GRID_C * GRID_C];

// Odd-parity pair array: O[m] = (src[2m+1], src[2m+2]) over the flat volume.
// 16.7M float2 = 134 MB device scratch.
__device__ float2 g_opairs[TOTAL / 2];

// ---------------------------------------------------------------------------
// Kernel 0: build odd pairs. Thread t handles 4 scalars -> 2 pairs (16B store).
// ---------------------------------------------------------------------------
__global__ void __launch_bounds__(256)
pair_kernel(const float* __restrict__ src) {
    size_t t    = (size_t)blockIdx.x * 256 + threadIdx.x;
    size_t base = t * 4;
    if (base >= TOTAL) return;
    float4 a = *(const float4*)(src + base);
    float  s = (base + 4 < TOTAL) ? __ldg(src + base + 4) : 0.0f;
    // O[2t] = (src[4t+1], src[4t+2]);  O[2t+1] = (src[4t+3], src[4t+4])
    float4 o = make_float4(a.y, a.z, a.w, s);
    *(float4*)((float*)g_opairs + base) = o;
}

// ---------------------------------------------------------------------------
// Kernel 1: axis-wise cumsum of the 8^3 coarse flow + per-channel offset.
// ---------------------------------------------------------------------------
__global__ void cumsum_kernel(const float* __restrict__ x,
                              const float* __restrict__ ox,
                              const float* __restrict__ oy,
                              const float* __restrict__ oz) {
    int t = blockIdx.x * blockDim.x + threadIdx.x;
    if (t >= NB * 3 * 64) return;
    int b = t / (3 * 64);
    int r = t % (3 * 64);
    int c = r / 64;
    int l = r % 64;

    float off = (c == 0) ? __ldg(ox) : (c == 1) ? __ldg(oy) : __ldg(oz);

    const float* src = x      + ((b * 3 + c) * 512);
    float*       dst = g_flow + ((b * 3 + c) * 512);

    int base, stride;
    if (c == 0)      { int d = l >> 3, h = l & 7; base = d * 64 + h * 8; stride = 1;  }
    else if (c == 1) { int d = l >> 3, w = l & 7; base = d * 64 + w;     stride = 8;  }
    else             { int h = l >> 3, w = l & 7; base = h * 8 + w;      stride = 64; }

    float acc = off;
#pragma unroll
    for (int i = 0; i < 8; i++) {
        acc += src[base + i * stride];
        dst[base + i * stride] = acc;
    }
}

// ---------------------------------------------------------------------------
// Kernel 2: fused trilinear-upsample of flow + trilinear grid-sample.
// Block = one output x-row (128 threads) at fixed (y, z, b)  [R4 best layout].
// Gather: per tap-row ONE aligned float2 from the even view (src) or the
// odd-pair array (g_opairs) -> 4 LDG.64 total, zero straddle loads.
// ---------------------------------------------------------------------------
__global__ void __launch_bounds__(VOX)
warp_kernel(const float* __restrict__ src, float* __restrict__ out) {
    const int x = threadIdx.x;
    const int y = blockIdx.x;
    const int z = blockIdx.y;
    const int b = blockIdx.z;

    __shared__ float s_c[3][2][2][GRID_C];   // [c][dz][dy][jx]
    __shared__ float s_row[3][GRID_C];

    const float inv16 = 0.0625f;
    float syf = fminf(fmaxf((y + 0.5f) * inv16 - 0.5f, 0.0f), 7.0f);
    float szf = fminf(fmaxf((z + 0.5f) * inv16 - 0.5f, 0.0f), 7.0f);
    int jy0 = min((int)syf, 6); float fy = syf - (float)jy0;
    int jz0 = min((int)szf, 6); float fz = szf - (float)jz0;

    if (threadIdx.x < 96) {
        int c    = threadIdx.x / 32;
        int rem  = threadIdx.x & 31;
        int corn = rem >> 3;
        int jx   = rem & 7;
        int dz   = corn >> 1, dy = corn & 1;
        const float* f = g_flow + ((b * 3 + c) * 512);
        s_c[c][dz][dy][jx] = f[(jz0 + dz) * 64 + (jy0 + dy) * 8 + jx];
    }
    __syncthreads();
    if (threadIdx.x < 24) {
        int c  = threadIdx.x >> 3;
        int jx = threadIdx.x & 7;
        float v0 = s_c[c][0][0][jx] + fy * (s_c[c][0][1][jx] - s_c[c][0][0][jx]);
        float v1 = s_c[c][1][0][jx] + fy * (s_c[c][1][1][jx] - s_c[c][1][0][jx]);
        s_row[c][jx] = v0 + fz * (v1 - v0);
    }
    __syncthreads();

    float sxf = fminf(fmaxf((x + 0.5f) * inv16 - 0.5f, 0.0f), 7.0f);
    int jx0 = min((int)sxf, 6); float fx = sxf - (float)jx0;

    float fl_x = s_row[0][jx0] + fx * (s_row[0][jx0 + 1] - s_row[0][jx0]);
    float fl_y = s_row[1][jx0] + fx * (s_row[1][jx0 + 1] - s_row[1][jx0]);
    float fl_z = s_row[2][jx0] + fx * (s_row[2][jx0 + 1] - s_row[2][jx0]);

    // grid_sample coords: g = ((flow + 1) * 128 - 1) * 0.5
    float gx = (fl_x + 1.0f) * 64.0f - 0.5f;
    float gy = (fl_y + 1.0f) * 64.0f - 0.5f;
    float gz = (fl_z + 1.0f) * 64.0f - 0.5f;

    float x0f = floorf(gx), y0f = floorf(gy), z0f = floorf(gz);
    int ix0 = (int)x0f, iy0 = (int)y0f, iz0 = (int)z0f;
    float fxs = gx - x0f, fys = gy - y0f, fzs = gz - z0f;

    // ---- unified-pair x-tap setup ----
    // pair(ix0) = (src[ix0], src[ix0+1]) lives at pair-index row*64 + (ix0>>1)
    // in the even view (ix0 even) or the odd-pair array (ix0 odd).
    // ix0 == -1: even view pair 0 = (src[0], src[1]); tap-b = .x, wa = 0.
    bool v0   = (unsigned)ix0       < (unsigned)VOX;
    bool v1   = (unsigned)(ix0 + 1) < (unsigned)VOX;
    bool xany = v0 | v1;
    bool odd  = v0 && (ix0 & 1);
    int  xp   = v0 ? (ix0 >> 1) : 0;
    float wa  = v0 ? (1.0f - fxs) : 0.0f;
    float wb  = v1 ? fxs          : 0.0f;

    const float2* Eb = (const float2*)(src + (size_t)b * VOX3);
    const float2* Ob = g_opairs + (size_t)b * (VOX3 / 2);
    const float2* P  = odd ? Ob : Eb;

    int base = (iz0 * VOX + iy0) * (VOX / 2) + xp;

    bool zv0 = (unsigned)iz0       < (unsigned)VOX;
    bool zv1 = (unsigned)(iz0 + 1) < (unsigned)VOX;
    bool yv0 = (unsigned)iy0       < (unsigned)VOX;
    bool yv1 = (unsigned)(iy0 + 1) < (unsigned)VOX;

    bool rv[4];
    rv[0] = zv0 & yv0 & xany;
    rv[1] = zv0 & yv1 & xany;
    rv[2] = zv1 & yv0 & xany;
    rv[3] = zv1 & yv1 & xany;
    const int off[4] = { 0, VOX / 2, VOX * VOX / 2, VOX * VOX / 2 + VOX / 2 };

    // 4 predicated aligned LDG.64, batched for MLP.
    float2 A[4];
#pragma unroll
    for (int k = 0; k < 4; k++) {
        A[k] = make_float2(0.0f, 0.0f);
        if (rv[k]) A[k] = __ldg(P + (base + off[k]));
    }

    float wy0 = 1.0f - fys, wy1 = fys;
    float wz0 = 1.0f - fzs, wz1 = fzs;
    float wk[4] = { wz0 * wy0, wz0 * wy1, wz1 * wy0, wz1 * wy1 };

    float acc = 0.0f;
#pragma unroll
    for (int k = 0; k < 4; k++) {
        float a  = A[k].x;
        float bb = v0 ? A[k].y : A[k].x;   // ix0 == -1: tap-b is .x
        acc += wk[k] * (wa * a + wb * bb);
    }

    out[(((size_t)b * VOX + z) * VOX + y) * VOX + x] = acc;
}

// ---------------------------------------------------------------------------
extern "C" void kernel_launch(void* const* d_in, const int* in_sizes, int n_in,
                              void* d_out, int out_size) {
    const float* x   = (const float*)d_in[0];   // (16,3,8,8,8)
    const float* src = (const float*)d_in[1];   // (16,128,128,128)
    const float* ox  = (const float*)d_in[2];   // scalar
    const float* oy  = (const float*)d_in[3];   // scalar
    const float* oz  = (const float*)d_in[4];   // scalar

    pair_kernel<<<TOTAL / 4 / 256, 256>>>(src);
    cumsum_kernel<<<12, 256>>>(x, ox, oy, oz);

    dim3 grid(VOX, VOX, NB);
    warp_kernel<<<grid, VOX>>>(src, (float*)d_out);
}

// round 9
// speedup vs baseline: 1.3633x; 1.3633x over previous
#include <cuda_runtime.h>

#define GRID_C 8
#define VOX    128
#define NB     16
#define ZT     16   // z-slices per block

// Coarse flow field after cumsum: [b][c][d][h][w], 16*3*512 floats = 96 KB
__device__ float g_flow[NB * 3 * GRID_C * GRID_C * GRID_C];

// ---------------------------------------------------------------------------
// Kernel 1: axis-wise cumsum of the 8^3 coarse flow + per-channel offset.
// ---------------------------------------------------------------------------
__global__ void cumsum_kernel(const float* __restrict__ x,
                              const float* __restrict__ ox,
                              const float* __restrict__ oy,
                              const float* __restrict__ oz) {
    int t = blockIdx.x * blockDim.x + threadIdx.x;
    if (t >= NB * 3 * 64) return;
    int b = t / (3 * 64);
    int r = t % (3 * 64);
    int c = r / 64;
    int l = r % 64;

    float off = (c == 0) ? __ldg(ox) : (c == 1) ? __ldg(oy) : __ldg(oz);

    const float* src = x      + ((b * 3 + c) * 512);
    float*       dst = g_flow + ((b * 3 + c) * 512);

    int base, stride;
    if (c == 0)      { int d = l >> 3, h = l & 7; base = d * 64 + h * 8; stride = 1;  }
    else if (c == 1) { int d = l >> 3, w = l & 7; base = d * 64 + w;     stride = 8;  }
    else             { int h = l >> 3, w = l & 7; base = h * 8 + w;      stride = 64; }

    float acc = off;
#pragma unroll
    for (int i = 0; i < 8; i++) {
        acc += src[base + i * stride];
        dst[base + i * stride] = acc;
    }
}

// ---------------------------------------------------------------------------
// Kernel 2: fused upsample + grid-sample, 16 z-slices per block.
// Block = x-row (128 threads) at fixed (y, z-tile, b).
// y-collapse staged once in smem (fy block-uniform); x-collapse per-thread
// once; per output the flow interp is 3 FMAs on u[c][zn] registers.
// ---------------------------------------------------------------------------
__global__ void __launch_bounds__(VOX)
warp_kernel(const float* __restrict__ src, float* __restrict__ out) {
    const int x  = threadIdx.x;
    const int y  = blockIdx.x;
    const int z0 = blockIdx.y * ZT;
    const int b  = blockIdx.z;

    __shared__ float s_cy[3][3][GRID_C];     // y-collapsed [c][zn][jx]

    const float inv16 = 0.0625f;
    float syf = fminf(fmaxf((y + 0.5f) * inv16 - 0.5f, 0.0f), 7.0f);
    int jy0 = min((int)syf, 6); float fy = syf - (float)jy0;

    float szf0 = fminf(fmaxf((z0 + 0.5f) * inv16 - 0.5f, 0.0f), 7.0f);
    int jz_base = min((int)szf0, 6);

    // Stage: 72 threads each load 2 y-neighbors of one (c, zn, jx) node and
    // collapse y. zn = jz_base + {0,1,2} clamped to node 7 (correct at the
    // fz=1 edge where only the clamped node is weighted).
    if (threadIdx.x < 72) {
        int c  = threadIdx.x / 24;
        int r  = threadIdx.x % 24;
        int zn = r >> 3;
        int jx = r & 7;
        int jz = min(jz_base + zn, 7);
        const float* f = g_flow + ((b * 3 + c) * 512) + jz * 64 + jy0 * 8 + jx;
        float a0 = f[0];
        float a1 = f[8];
        s_cy[c][zn][jx] = a0 + fy * (a1 - a0);
    }
    __syncthreads();

    // Per-thread x-collapse (fixed across the z loop).
    float sxf = fminf(fmaxf((x + 0.5f) * inv16 - 0.5f, 0.0f), 7.0f);
    int jx0 = min((int)sxf, 6); float fx = sxf - (float)jx0;

    float u[3][3];
#pragma unroll
    for (int c = 0; c < 3; c++)
#pragma unroll
        for (int zn = 0; zn < 3; zn++) {
            float a0 = s_cy[c][zn][jx0];
            float a1 = s_cy[c][zn][jx0 + 1];
            u[c][zn] = a0 + fx * (a1 - a0);
        }

    const float2* sb2 = (const float2*)(src + (size_t)b * (VOX * VOX * VOX));
    float* orow = out + (((size_t)b * VOX + z0) * VOX + y) * VOX + x;
    const int off4[4] = { 0, VOX / 2, VOX * VOX / 2, VOX * VOX / 2 + VOX / 2 };

#pragma unroll 4
    for (int zi = 0; zi < ZT; zi++) {
        int z = z0 + zi;
        float szf = fminf(fmaxf((z + 0.5f) * inv16 - 0.5f, 0.0f), 7.0f);
        int jz0 = min((int)szf, 6);
        float fz = szf - (float)jz0;
        int k = jz0 - jz_base;               // 0 or 1

        float fl0 = k ? (u[0][1] + fz * (u[0][2] - u[0][1]))
                      : (u[0][0] + fz * (u[0][1] - u[0][0]));
        float fl1 = k ? (u[1][1] + fz * (u[1][2] - u[1][1]))
                      : (u[1][0] + fz * (u[1][1] - u[1][0]));
        float fl2 = k ? (u[2][1] + fz * (u[2][2] - u[2][1]))
                      : (u[2][0] + fz * (u[2][1] - u[2][0]));

        float gx = (fl0 + 1.0f) * 64.0f - 0.5f;
        float gy = (fl1 + 1.0f) * 64.0f - 0.5f;
        float gz = (fl2 + 1.0f) * 64.0f - 0.5f;

        float x0f = floorf(gx), y0f = floorf(gy), z0f = floorf(gz);
        int ix0 = (int)x0f, iy0 = (int)y0f, iz0 = (int)z0f;
        float fxs = gx - x0f, fys = gy - y0f, fzs = gz - z0f;

        bool v0   = (unsigned)ix0       < (unsigned)VOX;
        bool v1   = (unsigned)(ix0 + 1) < (unsigned)VOX;
        bool xany = v0 | v1;
        int  e0   = (v0 ? ix0 : (ix0 + 1)) >> 1;
        bool odd  = (ix0 & 1) && v0;
        float wa  = v0 ? (1.0f - fxs) : 0.0f;
        float wb  = v1 ? fxs          : 0.0f;

        int base = iz0 * (VOX * VOX / 2) + iy0 * (VOX / 2) + e0;

        bool zv0 = (unsigned)iz0       < (unsigned)VOX;
        bool zv1 = (unsigned)(iz0 + 1) < (unsigned)VOX;
        bool yv0 = (unsigned)iy0       < (unsigned)VOX;
        bool yv1 = (unsigned)(iy0 + 1) < (unsigned)VOX;

        bool rv[4];
        rv[0] = zv0 & yv0 & xany;
        rv[1] = zv0 & yv1 & xany;
        rv[2] = zv1 & yv0 & xany;
        rv[3] = zv1 & yv1 & xany;

        float2 A[4];
#pragma unroll
        for (int kk = 0; kk < 4; kk++) {
            A[kk] = make_float2(0.0f, 0.0f);
            if (rv[kk]) A[kk] = __ldg(sb2 + (base + off4[kk]));
        }
        bool need2 = odd & v1;
        float Bx[4];
#pragma unroll
        for (int kk = 0; kk < 4; kk++) {
            Bx[kk] = 0.0f;
            if (rv[kk] & need2) Bx[kk] = __ldg((const float*)(sb2 + (base + off4[kk] + 1)));
        }

        float wy0 = 1.0f - fys, wy1 = fys;
        float wz0 = 1.0f - fzs, wz1 = fzs;
        float wk[4] = { wz0 * wy0, wz0 * wy1, wz1 * wy0, wz1 * wy1 };

        float acc = 0.0f;
#pragma unroll
        for (int kk = 0; kk < 4; kk++) {
            float a  = odd ? A[kk].y : A[kk].x;
            float bb = odd ? Bx[kk]  : A[kk].y;
            if (!v0) bb = A[kk].x;
            acc += wk[kk] * (wa * a + wb * bb);
        }

        orow[(size_t)zi * (VOX * VOX)] = acc;
    }
}

// ---------------------------------------------------------------------------
extern "C" void kernel_launch(void* const* d_in, const int* in_sizes, int n_in,
                              void* d_out, int out_size) {
    const float* x   = (const float*)d_in[0];   // (16,3,8,8,8)
    const float* src = (const float*)d_in[1];   // (16,128,128,128)
    const float* ox  = (const float*)d_in[2];   // scalar
    const float* oy  = (const float*)d_in[3];   // scalar
    const float* oz  = (const float*)d_in[4];   // scalar

    cumsum_kernel<<<12, 256>>>(x, ox, oy, oz);

    dim3 grid(VOX, VOX / ZT, NB);
    warp_kernel<<<grid, VOX>>>(src, (float*)d_out);
}

// round 11
// speedup vs baseline: 1.5849x; 1.1626x over previous
#include <cuda_runtime.h>
#include <cuda_fp16.h>

#define GRID_C 8
#define VOX    128
#define NB     16
#define ZT     16   // z-slices per block
#define VOX3   (VOX * VOX * VOX)
#define TOTAL  (NB * VOX3)

// Coarse flow field after cumsum: [b][c][d][h][w], 16*3*512 floats = 96 KB
__device__ float g_flow[NB * 3 * GRID_C * GRID_C * GRID_C];

// Quad volume: Q[flat(b,z,y,x)] = fp16x4 { s[z][y][x], s[z][y][x+1],
//                                          s[z][y+1][x], s[z][y+1][x+1] }
// packed as uint2 (.x = row-y x-pair, .y = row-y+1 x-pair). 268 MB.
__device__ uint2 g_q[TOTAL];

// ---------------------------------------------------------------------------
// Kernel 0: build the quad volume. Thread -> 4 consecutive x entries (32 B).
// ---------------------------------------------------------------------------
__global__ void __launch_bounds__(256)
qbuild_kernel(const float* __restrict__ src) {
    int g   = blockIdx.x * 256 + threadIdx.x;   // 8.39M threads
    int x0  = (g & 31) * 4;
    int row = g >> 5;                           // flat (b,z,y) row index
    int y   = row & (VOX - 1);
    int rb  = row << 7;                         // row base (float index)

    float4 a = *(const float4*)(src + rb + x0);
    int r1 = (y < VOX - 1) ? rb + VOX : rb;     // clamped y+1 row (weight-0 at edge)
    float4 c = *(const float4*)(src + r1 + x0);
    int ia4 = rb + x0 + 4; if (ia4 >= TOTAL) ia4 = TOTAL - 1;
    int ic4 = r1 + x0 + 4; if (ic4 >= TOTAL) ic4 = TOTAL - 1;
    float a4 = __ldg(src + ia4);                // x+1 of last lane (weight-0 at x=127)
    float c4 = __ldg(src + ic4);

    float ax[5] = { a.x, a.y, a.z, a.w, a4 };
    float cx[5] = { c.x, c.y, c.z, c.w, c4 };

    unsigned int ob[8];
#pragma unroll
    for (int j = 0; j < 4; j++) {
        __half2 lo = __floats2half2_rn(ax[j], ax[j + 1]);
        __half2 hi = __floats2half2_rn(cx[j], cx[j + 1]);
        ob[2 * j]     = *reinterpret_cast<unsigned int*>(&lo);
        ob[2 * j + 1] = *reinterpret_cast<unsigned int*>(&hi);
    }
    uint4* dst = (uint4*)(g_q + rb + x0);
    dst[0] = make_uint4(ob[0], ob[1], ob[2], ob[3]);
    dst[1] = make_uint4(ob[4], ob[5], ob[6], ob[7]);
}

// ---------------------------------------------------------------------------
// Kernel 1: axis-wise cumsum of the 8^3 coarse flow + per-channel offset.
// ---------------------------------------------------------------------------
__global__ void cumsum_kernel(const float* __restrict__ x,
                              const float* __restrict__ ox,
                              const float* __restrict__ oy,
                              const float* __restrict__ oz) {
    int t = blockIdx.x * blockDim.x + threadIdx.x;
    if (t >= NB * 3 * 64) return;
    int b = t / (3 * 64);
    int r = t % (3 * 64);
    int c = r / 64;
    int l = r % 64;

    float off = (c == 0) ? __ldg(ox) : (c == 1) ? __ldg(oy) : __ldg(oz);

    const float* src = x      + ((b * 3 + c) * 512);
    float*       dst = g_flow + ((b * 3 + c) * 512);

    int base, stride;
    if (c == 0)      { int d = l >> 3, h = l & 7; base = d * 64 + h * 8; stride = 1;  }
    else if (c == 1) { int d = l >> 3, w = l & 7; base = d * 64 + w;     stride = 8;  }
    else             { int h = l >> 3, w = l & 7; base = h * 8 + w;      stride = 64; }

    float acc = off;
#pragma unroll
    for (int i = 0; i < 8; i++) {
        acc += src[base + i * stride];
        dst[base + i * stride] = acc;
    }
}

// ---------------------------------------------------------------------------
// Kernel 2: fused upsample + grid-sample, 16 z-slices per block, gathering
// from the quad volume: TWO predicated 8-byte loads per output.
// ---------------------------------------------------------------------------
__global__ void __launch_bounds__(VOX)
warp_kernel(float* __restrict__ out) {
    const int x  = threadIdx.x;
    const int y  = blockIdx.x;
    const int z0 = blockIdx.y * ZT;
    const int b  = blockIdx.z;

    __shared__ float s_cy[3][3][GRID_C];     // y-collapsed [c][zn][jx]

    const float inv16 = 0.0625f;
    float syf = fminf(fmaxf((y + 0.5f) * inv16 - 0.5f, 0.0f), 7.0f);
    int jy0 = min((int)syf, 6); float fy = syf - (float)jy0;

    float szf0 = fminf(fmaxf((z0 + 0.5f) * inv16 - 0.5f, 0.0f), 7.0f);
    int jz_base = min((int)szf0, 6);

    if (threadIdx.x < 72) {
        int c  = threadIdx.x / 24;
        int r  = threadIdx.x % 24;
        int zn = r >> 3;
        int jx = r & 7;
        int jz = min(jz_base + zn, 7);
        const float* f = g_flow + ((b * 3 + c) * 512) + jz * 64 + jy0 * 8 + jx;
        float a0 = f[0];
        float a1 = f[8];
        s_cy[c][zn][jx] = a0 + fy * (a1 - a0);
    }
    __syncthreads();

    float sxf = fminf(fmaxf((x + 0.5f) * inv16 - 0.5f, 0.0f), 7.0f);
    int jx0 = min((int)sxf, 6); float fx = sxf - (float)jx0;

    float u[3][3];
#pragma unroll
    for (int c = 0; c < 3; c++)
#pragma unroll
        for (int zn = 0; zn < 3; zn++) {
            float a0 = s_cy[c][zn][jx0];
            float a1 = s_cy[c][zn][jx0 + 1];
            u[c][zn] = a0 + fx * (a1 - a0);
        }

    const uint2* qb = g_q + (size_t)b * VOX3;
    float* orow = out + (((size_t)b * VOX + z0) * VOX + y) * VOX + x;

#pragma unroll 4
    for (int zi = 0; zi < ZT; zi++) {
        int z = z0 + zi;
        float szf = fminf(fmaxf((z + 0.5f) * inv16 - 0.5f, 0.0f), 7.0f);
        int jzq = min((int)szf, 6);
        float fz = szf - (float)jzq;
        int k = jzq - jz_base;               // 0 or 1

        float fl0 = k ? (u[0][1] + fz * (u[0][2] - u[0][1]))
                      : (u[0][0] + fz * (u[0][1] - u[0][0]));
        float fl1 = k ? (u[1][1] + fz * (u[1][2] - u[1][1]))
                      : (u[1][0] + fz * (u[1][1] - u[1][0]));
        float fl2 = k ? (u[2][1] + fz * (u[2][2] - u[2][1]))
                      : (u[2][0] + fz * (u[2][1] - u[2][0]));

        float gx = (fl0 + 1.0f) * 64.0f - 0.5f;
        float gy = (fl1 + 1.0f) * 64.0f - 0.5f;
        float gz = (fl2 + 1.0f) * 64.0f - 0.5f;

        float x0f = floorf(gx), y0f = floorf(gy), z0f = floorf(gz);
        int ix0 = (int)x0f, iy0 = (int)y0f, iz0 = (int)z0f;
        float fxs = gx - x0f, fys = gy - y0f, fzs = gz - z0f;

        bool v0 = (unsigned)ix0       < (unsigned)VOX;
        bool v1 = (unsigned)(ix0 + 1) < (unsigned)VOX;
        bool yv0 = (unsigned)iy0       < (unsigned)VOX;
        bool yv1 = (unsigned)(iy0 + 1) < (unsigned)VOX;
        bool zv0 = (unsigned)iz0       < (unsigned)VOX;
        bool zv1 = (unsigned)(iz0 + 1) < (unsigned)VOX;
        bool xany = v0 | v1;
        bool yany = yv0 | yv1;
        bool pany = xany & yany;

        int xc = v0  ? ix0 : 0;              // ix0 = -1 -> 0
        int yc = yv0 ? iy0 : 0;              // iy0 = -1 -> 0
        int pbase = (yc << 7) + xc;          // within-plane quad index

        // Two predicated 8B loads, batched for MLP.
        uint2 q0 = make_uint2(0u, 0u), q1 = make_uint2(0u, 0u);
        if (pany & zv0) q0 = __ldg(qb + ((iz0 << 14) + pbase));
        if (pany & zv1) q1 = __ldg(qb + (((iz0 + 1) << 14) + pbase));

        float wa  = v0  ? (1.0f - fxs) : 0.0f;
        float wb  = v1  ? fxs          : 0.0f;
        float wy0 = yv0 ? (1.0f - fys) : 0.0f;
        float wy1 = yv1 ? fys          : 0.0f;
        float wz0 = zv0 ? (1.0f - fzs) : 0.0f;
        float wz1 = zv1 ? fzs          : 0.0f;

        float acc;
        {
            __half2 h0lo = *reinterpret_cast<__half2*>(&q0.x);
            __half2 h0hi = *reinterpret_cast<__half2*>(&q0.y);
            __half2 h1lo = *reinterpret_cast<__half2*>(&q1.x);
            __half2 h1hi = *reinterpret_cast<__half2*>(&q1.y);
            float2 p0r0 = __half22float2(h0lo);
            float2 p0r1 = __half22float2(h0hi);
            float2 p1r0 = __half22float2(h1lo);
            float2 p1r1 = __half22float2(h1hi);
            if (!yv0) { p0r1 = p0r0; p1r1 = p1r0; }  // iy0 = -1: row1 = volume row 0

            float p0a0 = p0r0.x, p0b0 = v0 ? p0r0.y : p0r0.x;
            float p0a1 = p0r1.x, p0b1 = v0 ? p0r1.y : p0r1.x;
            float p1a0 = p1r0.x, p1b0 = v0 ? p1r0.y : p1r0.x;
            float p1a1 = p1r1.x, p1b1 = v0 ? p1r1.y : p1r1.x;

            float vp0 = wy0 * (wa * p0a0 + wb * p0b0) + wy1 * (wa * p0a1 + wb * p0b1);
            float vp1 = wy0 * (wa * p1a0 + wb * p1b0) + wy1 * (wa * p1a1 + wb * p1b1);
            acc = wz0 * vp0 + wz1 * vp1;
        }

        orow[(size_t)zi * (VOX * VOX)] = acc;
    }
}

// ---------------------------------------------------------------------------
extern "C" void kernel_launch(void* const* d_in, const int* in_sizes, int n_in,
                              void* d_out, int out_size) {
    const float* x   = (const float*)d_in[0];   // (16,3,8,8,8)
    const float* src = (const float*)d_in[1];   // (16,128,128,128)
    const float* ox  = (const float*)d_in[2];   // scalar
    const float* oy  = (const float*)d_in[3];   // scalar
    const float* oz  = (const float*)d_in[4];   // scalar

    qbuild_kernel<<<TOTAL / 4 / 256, 256>>>(src);
    cumsum_kernel<<<12, 256>>>(x, ox, oy, oz);

    dim3 grid(VOX, VOX / ZT, NB);
    warp_kernel<<<grid, VOX>>>((float*)d_out);
}